// round 16
// baseline (speedup 1.0000x reference)
#include <cuda_runtime.h>
#include <cuda_bf16.h>
#include <math.h>
#include <stdint.h>

#define S_LEN  2048
#define BATCH  4
#define NHEAD  16
#define DMODEL 1024
#define DHEAD  64
#define MROWS  (BATCH * S_LEN)   // 8192
#define NZ     (BATCH * NHEAD)   // 64
#define LDHL   (NHEAD * 128)     // 2048 bf16 per row: per head hi(64)|lo(64)
#define LD2    (2 * DMODEL)      // 2048: hi|lo plane row stride

// ---------------- scratch (no allocations allowed) ----------------
__device__ __nv_bfloat16 g_qs[(size_t)MROWS * LDHL];  // per-head compact q hi|lo
__device__ __nv_bfloat16 g_ks[(size_t)MROWS * LDHL];  // per-head compact k hi|lo
__device__ __nv_bfloat16 g_q2[(size_t)MROWS * LD2];   // q input planes [row][hi|lo]
__device__ __nv_bfloat16 g_k2[(size_t)MROWS * LD2];   // k input planes
__device__ __nv_bfloat16 g_wq2[(size_t)DMODEL * LD2]; // w_q planes [out][hi|lo]
__device__ __nv_bfloat16 g_wk2[(size_t)DMODEL * LD2]; // w_k planes
__device__ float g_vp[(size_t)MROWS * DMODEL];        // tf32-rounded V proj
__device__ float g_ao[(size_t)MROWS * DMODEL];        // tf32-rounded PV out
__device__ float g_wf[(size_t)DMODEL * DMODEL];       // tf32-rounded w_fc
__device__ float g_sinv[(size_t)NZ * S_LEN];          // 1/rowsum

// ---------------- helpers ----------------
__device__ __forceinline__ void mma_tf32(float c[4], const uint32_t a[4], const uint32_t b[2]) {
    asm volatile(
        "mma.sync.aligned.m16n8k8.row.col.f32.tf32.tf32.f32 "
        "{%0,%1,%2,%3}, {%4,%5,%6,%7}, {%8,%9}, {%0,%1,%2,%3};\n"
        : "+f"(c[0]), "+f"(c[1]), "+f"(c[2]), "+f"(c[3])
        : "r"(a[0]), "r"(a[1]), "r"(a[2]), "r"(a[3]), "r"(b[0]), "r"(b[1]));
}
__device__ __forceinline__ void mma_bf16(float c[4], const uint32_t a[4], const uint32_t b[2]) {
    asm volatile(
        "mma.sync.aligned.m16n8k16.row.col.f32.bf16.bf16.f32 "
        "{%0,%1,%2,%3}, {%4,%5,%6,%7}, {%8,%9}, {%0,%1,%2,%3};\n"
        : "+f"(c[0]), "+f"(c[1]), "+f"(c[2]), "+f"(c[3])
        : "r"(a[0]), "r"(a[1]), "r"(a[2]), "r"(a[3]), "r"(b[0]), "r"(b[1]));
}
__device__ __forceinline__ uint32_t f2tf32(float x) {
    uint32_t r;
    asm("cvt.rna.tf32.f32 %0, %1;\n" : "=r"(r) : "f"(x));
    return r;
}
__device__ __forceinline__ void cp_async16(uint32_t smem_addr, const void* gptr) {
    asm volatile("cp.async.cg.shared.global [%0], [%1], 16;\n" :: "r"(smem_addr), "l"(gptr));
}
__device__ __forceinline__ void cp_commit() { asm volatile("cp.async.commit_group;\n"); }
template <int N> __device__ __forceinline__ void cp_wait() {
    asm volatile("cp.async.wait_group %0;\n" :: "n"(N));
}

// =================================================================
// Split fp32 -> bf16 hi|lo planes.
// =================================================================
__global__ __launch_bounds__(256) void split_planes(
    const float* __restrict__ x, __nv_bfloat16* __restrict__ o, int rows)
{
    const int n4 = rows * (DMODEL / 4);
    int idx = blockIdx.x * 256 + threadIdx.x;
    if (idx >= n4) return;
    const int row = idx / (DMODEL / 4);
    const int c4  = idx % (DMODEL / 4);
    const float4 v = ((const float4*)x)[idx];
    __nv_bfloat16 h[4], l[4];
    h[0] = __float2bfloat16(v.x); l[0] = __float2bfloat16(v.x - __bfloat162float(h[0]));
    h[1] = __float2bfloat16(v.y); l[1] = __float2bfloat16(v.y - __bfloat162float(h[1]));
    h[2] = __float2bfloat16(v.z); l[2] = __float2bfloat16(v.z - __bfloat162float(h[2]));
    h[3] = __float2bfloat16(v.w); l[3] = __float2bfloat16(v.w - __bfloat162float(h[3]));
    *(uint2*)(o + (size_t)row * LD2 + c4 * 4)          = *(const uint2*)h;
    *(uint2*)(o + (size_t)row * LD2 + DMODEL + c4 * 4) = *(const uint2*)l;
}

// =================================================================
// Round fp32 array to tf32-representable fp32.
// =================================================================
__global__ __launch_bounds__(256) void round_tf32_kernel(
    const float* __restrict__ x, float* __restrict__ o, int n4)
{
    int idx = blockIdx.x * 256 + threadIdx.x;
    if (idx >= n4) return;
    float4 v = ((const float4*)x)[idx];
    v.x = __uint_as_float(f2tf32(v.x));
    v.y = __uint_as_float(f2tf32(v.y));
    v.z = __uint_as_float(f2tf32(v.z));
    v.w = __uint_as_float(f2tf32(v.w));
    ((float4*)o)[idx] = v;
}

// =================================================================
// Q/K projection: zero-ALU bf16x3 GEMM over precomputed planes.
// =================================================================
#define PS 40   // bf16 smem row stride (32 + 8 pad)

__global__ __launch_bounds__(256, 2) void proj_bf16_kernel(
    const __nv_bfloat16* __restrict__ A2,
    const __nv_bfloat16* __restrict__ B2,
    __nv_bfloat16* __restrict__ C)
{
    constexpr int BM = 128, BN = 64, BK = 32;
    constexpr int APL = BM * PS;
    constexpr int BPL = BN * PS;
    constexpr int STAGE = 2 * APL + 2 * BPL;

    extern __shared__ __nv_bfloat16 smemb[];

    const int tid  = threadIdx.x;
    const int warp = tid >> 5;
    const int lane = tid & 31;
    const int g = lane >> 2;
    const int t = lane & 3;
    const int wm0 = (warp >> 1) * 32;
    const int wn0 = (warp & 1) * 32;
    const int bm = blockIdx.y * BM, bn = blockIdx.x * BN;

    float acc[2][4][4];
#pragma unroll
    for (int i = 0; i < 2; i++)
#pragma unroll
        for (int j = 0; j < 4; j++)
#pragma unroll
            for (int r = 0; r < 4; r++) acc[i][j][r] = 0.0f;

    auto load_tile = [&](int it, int stage) {
        __nv_bfloat16* Ah = smemb + stage * STAGE;
        __nv_bfloat16* Al = Ah + APL;
        __nv_bfloat16* Bh = Al + APL;
        __nv_bfloat16* Bl = Bh + BPL;
        const int k0 = it * BK;
#pragma unroll
        for (int i = tid; i < BM * 4; i += 256) {
            const int r = i >> 2, c = (i & 3) * 8;
            const __nv_bfloat16* src = A2 + (size_t)(bm + r) * LD2 + k0 + c;
            cp_async16((uint32_t)__cvta_generic_to_shared(Ah + r * PS + c), src);
            cp_async16((uint32_t)__cvta_generic_to_shared(Al + r * PS + c), src + DMODEL);
        }
#pragma unroll
        for (int i = tid; i < BN * 4; i += 256) {
            const int r = i >> 2, c = (i & 3) * 8;
            const __nv_bfloat16* src = B2 + (size_t)(bn + r) * LD2 + k0 + c;
            cp_async16((uint32_t)__cvta_generic_to_shared(Bh + r * PS + c), src);
            cp_async16((uint32_t)__cvta_generic_to_shared(Bl + r * PS + c), src + DMODEL);
        }
    };

    load_tile(0, 0);
    cp_commit();

    constexpr int nIter = DMODEL / BK;   // 32
    for (int it = 0; it < nIter; it++) {
        if (it + 1 < nIter) {
            load_tile(it + 1, (it + 1) & 1);
            cp_commit();
            cp_wait<1>();
        } else {
            cp_wait<0>();
        }
        __syncthreads();

        const __nv_bfloat16* Ah = smemb + (it & 1) * STAGE;
        const __nv_bfloat16* Al = Ah + APL;
        const __nv_bfloat16* Bh = Al + APL;
        const __nv_bfloat16* Bl = Bh + BPL;

#pragma unroll
        for (int ks = 0; ks < 2; ks++) {
            const int k0 = ks * 16;
            uint32_t a_h[2][4], a_l[2][4], b_h[4][2], b_l[4][2];
#pragma unroll
            for (int mi = 0; mi < 2; mi++) {
                const int r0 = wm0 + mi * 16 + g;
                const int o0 = r0 * PS + k0 + 2 * t;
                const int o1 = (r0 + 8) * PS + k0 + 2 * t;
                a_h[mi][0] = *(const uint32_t*)(Ah + o0);
                a_h[mi][1] = *(const uint32_t*)(Ah + o1);
                a_h[mi][2] = *(const uint32_t*)(Ah + o0 + 8);
                a_h[mi][3] = *(const uint32_t*)(Ah + o1 + 8);
                a_l[mi][0] = *(const uint32_t*)(Al + o0);
                a_l[mi][1] = *(const uint32_t*)(Al + o1);
                a_l[mi][2] = *(const uint32_t*)(Al + o0 + 8);
                a_l[mi][3] = *(const uint32_t*)(Al + o1 + 8);
            }
#pragma unroll
            for (int ni = 0; ni < 4; ni++) {
                const int n0 = wn0 + ni * 8 + g;
                const int ob = n0 * PS + k0 + 2 * t;
                b_h[ni][0] = *(const uint32_t*)(Bh + ob);
                b_h[ni][1] = *(const uint32_t*)(Bh + ob + 8);
                b_l[ni][0] = *(const uint32_t*)(Bl + ob);
                b_l[ni][1] = *(const uint32_t*)(Bl + ob + 8);
            }
#pragma unroll
            for (int mi = 0; mi < 2; mi++)
#pragma unroll
                for (int ni = 0; ni < 4; ni++) {
                    mma_bf16(acc[mi][ni], a_l[mi], b_h[ni]);
                    mma_bf16(acc[mi][ni], a_h[mi], b_l[ni]);
                    mma_bf16(acc[mi][ni], a_h[mi], b_h[ni]);
                }
        }
        __syncthreads();
    }

#pragma unroll
    for (int mi = 0; mi < 2; mi++) {
#pragma unroll
        for (int ni = 0; ni < 4; ni++) {
            const long long row0 = bm + wm0 + mi * 16 + g;
            const long long col0 = bn + wn0 + ni * 8 + t * 2;
#pragma unroll
            for (int e = 0; e < 4; e++) {
                const long long row = row0 + (e >> 1) * 8;
                const int col = (int)col0 + (e & 1);
                const float val = acc[mi][ni][e];
                const __nv_bfloat16 hi = __float2bfloat16(val);
                const __nv_bfloat16 lo = __float2bfloat16(val - __bfloat162float(hi));
                const long long base = row * LDHL + (col >> 6) * 128 + (col & 63);
                C[base     ] = hi;
                C[base + 64] = lo;
            }
        }
    }
}

// =================================================================
// Generic tensor-core tf32 GEMM (V proj, fc).
// =================================================================
template <bool TRANSB, bool RES, bool RND, bool PT>
__global__ __launch_bounds__(256, 2) void gemm_tc(
    const float* __restrict__ A, int lda,
    const float* __restrict__ B, int ldb,
    float* __restrict__ C, int ldc,
    int K, float alpha, const float* __restrict__ Res)
{
    constexpr int BM = 128, BN = 64, BK = 32;
    constexpr int MI = 2, NI = 4;
    constexpr int A_WORDS = BM * (BK + 4);
    constexpr int B_WORDS = TRANSB ? BN * (BK + 4) : BK * (BN + 4);
    constexpr int STAGE_WORDS = A_WORDS + B_WORDS;

    extern __shared__ float smemf[];

    const int tid  = threadIdx.x;
    const int warp = tid >> 5;
    const int lane = tid & 31;
    const int g = lane >> 2;
    const int t = lane & 3;
    const int wm0 = (warp >> 1) * 32;
    const int wn0 = (warp & 1) * 32;
    const int bm = blockIdx.y * BM, bn = blockIdx.x * BN;

    float acc[MI][NI][4];
#pragma unroll
    for (int i = 0; i < MI; i++)
#pragma unroll
        for (int j = 0; j < NI; j++)
#pragma unroll
            for (int r = 0; r < 4; r++) acc[i][j][r] = 0.0f;

    const int nIter = K / BK;

    auto load_tile = [&](int it, int stage) {
        float* As = smemf + stage * STAGE_WORDS;
        float* Bs = As + A_WORDS;
        const int k0 = it * BK;
#pragma unroll
        for (int i = tid; i < BM * BK / 4; i += 256) {
            int r = i / 8, c = (i % 8) * 4;
            uint32_t dst = (uint32_t)__cvta_generic_to_shared(As + r * (BK + 4) + c);
            cp_async16(dst, A + (long long)(bm + r) * lda + k0 + c);
        }
        if (TRANSB) {
#pragma unroll
            for (int i = tid; i < BN * BK / 4; i += 256) {
                int r = i / 8, c = (i % 8) * 4;
                uint32_t dst = (uint32_t)__cvta_generic_to_shared(Bs + r * (BK + 4) + c);
                cp_async16(dst, B + (long long)(bn + r) * ldb + k0 + c);
            }
        } else {
#pragma unroll
            for (int i = tid; i < BK * BN / 4; i += 256) {
                int r = i / 16, c = (i % 16) * 4;
                uint32_t dst = (uint32_t)__cvta_generic_to_shared(Bs + r * (BN + 4) + c);
                cp_async16(dst, B + (long long)(k0 + r) * ldb + bn + c);
            }
        }
    };

    load_tile(0, 0);
    cp_commit();

    for (int it = 0; it < nIter; it++) {
        if (it + 1 < nIter) {
            load_tile(it + 1, (it + 1) & 1);
            cp_commit();
            cp_wait<1>();
        } else {
            cp_wait<0>();
        }
        __syncthreads();

        const float* As = smemf + (it & 1) * STAGE_WORDS;
        const float* Bs = As + A_WORDS;

#pragma unroll
        for (int ks = 0; ks < BK / 8; ks++) {
            uint32_t ah[MI][4], bh[NI][2];
#pragma unroll
            for (int mi = 0; mi < MI; mi++) {
                const int r0 = wm0 + mi * 16 + g;
                const int c0 = ks * 8 + t;
                if (PT) {
                    ah[mi][0] = __float_as_uint(As[(r0    ) * (BK + 4) + c0    ]);
                    ah[mi][1] = __float_as_uint(As[(r0 + 8) * (BK + 4) + c0    ]);
                    ah[mi][2] = __float_as_uint(As[(r0    ) * (BK + 4) + c0 + 4]);
                    ah[mi][3] = __float_as_uint(As[(r0 + 8) * (BK + 4) + c0 + 4]);
                } else {
                    ah[mi][0] = f2tf32(As[(r0    ) * (BK + 4) + c0    ]);
                    ah[mi][1] = f2tf32(As[(r0 + 8) * (BK + 4) + c0    ]);
                    ah[mi][2] = f2tf32(As[(r0    ) * (BK + 4) + c0 + 4]);
                    ah[mi][3] = f2tf32(As[(r0 + 8) * (BK + 4) + c0 + 4]);
                }
            }
#pragma unroll
            for (int ni = 0; ni < NI; ni++) {
                const int n0 = wn0 + ni * 8 + g;
                float b0, b1;
                if (TRANSB) {
                    b0 = Bs[n0 * (BK + 4) + ks * 8 + t    ];
                    b1 = Bs[n0 * (BK + 4) + ks * 8 + t + 4];
                } else {
                    b0 = Bs[(ks * 8 + t    ) * (BN + 4) + n0];
                    b1 = Bs[(ks * 8 + t + 4) * (BN + 4) + n0];
                }
                if (PT) {
                    bh[ni][0] = __float_as_uint(b0);
                    bh[ni][1] = __float_as_uint(b1);
                } else {
                    bh[ni][0] = f2tf32(b0);
                    bh[ni][1] = f2tf32(b1);
                }
            }
#pragma unroll
            for (int mi = 0; mi < MI; mi++)
#pragma unroll
                for (int ni = 0; ni < NI; ni++)
                    mma_tf32(acc[mi][ni], ah[mi], bh[ni]);
        }
        __syncthreads();
    }

#pragma unroll
    for (int mi = 0; mi < MI; mi++) {
#pragma unroll
        for (int ni = 0; ni < NI; ni++) {
            const long long row0 = bm + wm0 + mi * 16 + g;
            const long long col0 = bn + wn0 + ni * 8 + t * 2;
            float2 v0, v1;
            v0.x = alpha * acc[mi][ni][0];
            v0.y = alpha * acc[mi][ni][1];
            v1.x = alpha * acc[mi][ni][2];
            v1.y = alpha * acc[mi][ni][3];
            if (RES) {
                const float2 r0 = *(const float2*)(Res + row0 * ldc + col0);
                const float2 r1 = *(const float2*)(Res + (row0 + 8) * ldc + col0);
                v0.x += r0.x; v0.y += r0.y;
                v1.x += r1.x; v1.y += r1.y;
            }
            if (RND) {
                v0.x = __uint_as_float(f2tf32(v0.x));
                v0.y = __uint_as_float(f2tf32(v0.y));
                v1.x = __uint_as_float(f2tf32(v1.x));
                v1.y = __uint_as_float(f2tf32(v1.y));
            }
            *(float2*)(C + row0 * ldc + col0) = v0;
            *(float2*)(C + (row0 + 8) * ldc + col0) = v1;
        }
    }
}

// =================================================================
// Shared scores-fragment helper macros/constants for pass1/pass2
// =================================================================
#define QKS 72   // bf16 stride for Q/K planes (64+8)
#define QPL (128 * QKS)   // Q plane elems
#define KPL (64 * QKS)    // K plane elems

// =================================================================
// Pass 1: full-row softmax denominators, no attn store.
// grid (S_LEN/128, NZ). 2 CTAs/SM.
// =================================================================
__global__ __launch_bounds__(256, 2) void sums_kernel(
    const __nv_bfloat16* __restrict__ qs, const __nv_bfloat16* __restrict__ ks_,
    float* __restrict__ sinv)
{
    extern __shared__ __nv_bfloat16 smemb[];
    __nv_bfloat16* Qh = smemb;            // 128*72
    __nv_bfloat16* Ql = Qh + QPL;
    __nv_bfloat16* Kb = Ql + QPL;         // 2 stages x (Kh|Kl)
    __shared__ float rowpart[2][128];

    const int strip = blockIdx.x;
    const int z = blockIdx.y;
    const int b = z >> 4, h = z & 15;
    const __nv_bfloat16* Aq = qs + (long long)b * S_LEN * LDHL + h * 128;
    const __nv_bfloat16* Bk = ks_ + (long long)b * S_LEN * LDHL + h * 128;
    const int bm = strip * 128;

    const int tid  = threadIdx.x;
    const int warp = tid >> 5;
    const int lane = tid & 31;
    const int g = lane >> 2;
    const int t = lane & 3;
    const int wm0 = (warp >> 1) * 32;
    const int wn0 = (warp & 1) * 32;
    const int wc  = warp & 1;

    auto load_k = [&](int jb, int stage) {
        __nv_bfloat16* Kh = Kb + stage * 2 * KPL;
        __nv_bfloat16* Kl = Kh + KPL;
#pragma unroll
        for (int i = tid; i < 64 * 8; i += 256) {
            const int r = i >> 3, c = (i & 7) * 8;
            const __nv_bfloat16* src = Bk + (long long)(jb * 64 + r) * LDHL + c;
            cp_async16((uint32_t)__cvta_generic_to_shared(Kh + r * QKS + c), src);
            cp_async16((uint32_t)__cvta_generic_to_shared(Kl + r * QKS + c), src + 64);
        }
    };

    // load Q planes + K block 0
#pragma unroll
    for (int i = tid; i < 128 * 8; i += 256) {
        const int r = i >> 3, c = (i & 7) * 8;
        const __nv_bfloat16* src = Aq + (long long)(bm + r) * LDHL + c;
        cp_async16((uint32_t)__cvta_generic_to_shared(Qh + r * QKS + c), src);
        cp_async16((uint32_t)__cvta_generic_to_shared(Ql + r * QKS + c), src + 64);
    }
    load_k(0, 0);
    cp_commit();
    cp_wait<0>();
    __syncthreads();

    float rsum[2][2] = {{0.f, 0.f}, {0.f, 0.f}};

    for (int jb = 0; jb < 32; jb++) {
        if (jb + 1 < 32) { load_k(jb + 1, (jb + 1) & 1); cp_commit(); }

        const __nv_bfloat16* Kh = Kb + (jb & 1) * 2 * KPL;
        const __nv_bfloat16* Kl = Kh + KPL;

        float acc[2][4][4];
#pragma unroll
        for (int i = 0; i < 2; i++)
#pragma unroll
            for (int j = 0; j < 4; j++)
#pragma unroll
                for (int r = 0; r < 4; r++) acc[i][j][r] = 0.0f;

#pragma unroll
        for (int ks = 0; ks < 4; ks++) {
            const int k0 = ks * 16;
            uint32_t a_h[2][4], a_l[2][4], b_h[4][2], b_l[4][2];
#pragma unroll
            for (int mi = 0; mi < 2; mi++) {
                const int r0 = wm0 + mi * 16 + g;
                const int o0 = r0 * QKS + k0 + 2 * t;
                const int o1 = (r0 + 8) * QKS + k0 + 2 * t;
                a_h[mi][0] = *(const uint32_t*)(Qh + o0);
                a_h[mi][1] = *(const uint32_t*)(Qh + o1);
                a_h[mi][2] = *(const uint32_t*)(Qh + o0 + 8);
                a_h[mi][3] = *(const uint32_t*)(Qh + o1 + 8);
                a_l[mi][0] = *(const uint32_t*)(Ql + o0);
                a_l[mi][1] = *(const uint32_t*)(Ql + o1);
                a_l[mi][2] = *(const uint32_t*)(Ql + o0 + 8);
                a_l[mi][3] = *(const uint32_t*)(Ql + o1 + 8);
            }
#pragma unroll
            for (int ni = 0; ni < 4; ni++) {
                const int n0 = wn0 + ni * 8 + g;
                const int ob = n0 * QKS + k0 + 2 * t;
                b_h[ni][0] = *(const uint32_t*)(Kh + ob);
                b_h[ni][1] = *(const uint32_t*)(Kh + ob + 8);
                b_l[ni][0] = *(const uint32_t*)(Kl + ob);
                b_l[ni][1] = *(const uint32_t*)(Kl + ob + 8);
            }
#pragma unroll
            for (int mi = 0; mi < 2; mi++)
#pragma unroll
                for (int ni = 0; ni < 4; ni++) {
                    mma_bf16(acc[mi][ni], a_l[mi], b_h[ni]);
                    mma_bf16(acc[mi][ni], a_h[mi], b_l[ni]);
                    mma_bf16(acc[mi][ni], a_h[mi], b_h[ni]);
                }
        }

#pragma unroll
        for (int mi = 0; mi < 2; mi++)
#pragma unroll
            for (int ni = 0; ni < 4; ni++) {
                rsum[mi][0] += __expf(0.125f * acc[mi][ni][0]) + __expf(0.125f * acc[mi][ni][1]);
                rsum[mi][1] += __expf(0.125f * acc[mi][ni][2]) + __expf(0.125f * acc[mi][ni][3]);
            }

        if (jb + 1 < 32) cp_wait<0>();
        __syncthreads();
    }

#pragma unroll
    for (int mi = 0; mi < 2; mi++)
#pragma unroll
        for (int s = 0; s < 2; s++) {
            float v = rsum[mi][s];
            v += __shfl_xor_sync(0xffffffffu, v, 1);
            v += __shfl_xor_sync(0xffffffffu, v, 2);
            if (t == 0) rowpart[wc][wm0 + mi * 16 + s * 8 + g] = v;
        }
    __syncthreads();
    if (tid < 128) {
        float s = rowpart[0][tid] + rowpart[1][tid];
        sinv[(long long)z * S_LEN + bm + tid] = 1.0f / s;
    }
}

// =================================================================
// Pass 2: recompute scores, normalize, write attn ONCE, and do PV
// through an smem P-tile. grid (S_LEN/128, NZ). 1 CTA/SM.
// =================================================================
#define PSTR 68   // fp32 stride for P and V tiles

__global__ __launch_bounds__(256, 1) void fused_kernel(
    const __nv_bfloat16* __restrict__ qs, const __nv_bfloat16* __restrict__ ks_,
    const float* __restrict__ vp, const float* __restrict__ sinv,
    float* __restrict__ attn, float* __restrict__ ao)
{
    extern __shared__ __nv_bfloat16 smemb[];
    __nv_bfloat16* Qh = smemb;                  // 128*72
    __nv_bfloat16* Ql = Qh + QPL;
    __nv_bfloat16* Kb = Ql + QPL;               // 2 x (Kh|Kl)
    float* Psm = (float*)(Kb + 2 * 2 * KPL);    // 128*68
    float* Vb  = Psm + 128 * PSTR;              // 2 x 64*68
    __shared__ float sInv[128];

    const int strip = blockIdx.x;
    const int z = blockIdx.y;
    const int b = z >> 4, h = z & 15;
    const __nv_bfloat16* Aq = qs + (long long)b * S_LEN * LDHL + h * 128;
    const __nv_bfloat16* Bk = ks_ + (long long)b * S_LEN * LDHL + h * 128;
    const float* V = vp + (long long)b * S_LEN * DMODEL + h * DHEAD;
    float* Ca = attn + (long long)z * S_LEN * S_LEN;
    float* Co = ao + (long long)b * S_LEN * DMODEL + h * DHEAD;
    const int bm = strip * 128;

    const int tid  = threadIdx.x;
    const int warp = tid >> 5;
    const int lane = tid & 31;
    const int g = lane >> 2;
    const int t = lane & 3;
    const int wm0 = (warp >> 1) * 32;
    const int wn0 = (warp & 1) * 32;

    if (tid < 128) sInv[tid] = sinv[(long long)z * S_LEN + bm + tid];

    auto load_kv = [&](int jb, int stage) {
        __nv_bfloat16* Kh = Kb + stage * 2 * KPL;
        __nv_bfloat16* Kl = Kh + KPL;
        float* Vs = Vb + stage * 64 * PSTR;
#pragma unroll
        for (int i = tid; i < 64 * 8; i += 256) {
            const int r = i >> 3, c = (i & 7) * 8;
            const __nv_bfloat16* src = Bk + (long long)(jb * 64 + r) * LDHL + c;
            cp_async16((uint32_t)__cvta_generic_to_shared(Kh + r * QKS + c), src);
            cp_async16((uint32_t)__cvta_generic_to_shared(Kl + r * QKS + c), src + 64);
        }
#pragma unroll
        for (int i = tid; i < 64 * 16; i += 256) {
            const int r = i >> 4, c4 = (i & 15) * 4;
            cp_async16((uint32_t)__cvta_generic_to_shared(Vs + r * PSTR + c4),
                       V + (long long)(jb * 64 + r) * DMODEL + c4);
        }
    };

    // load Q planes + block 0
#pragma unroll
    for (int i = tid; i < 128 * 8; i += 256) {
        const int r = i >> 3, c = (i & 7) * 8;
        const __nv_bfloat16* src = Aq + (long long)(bm + r) * LDHL + c;
        cp_async16((uint32_t)__cvta_generic_to_shared(Qh + r * QKS + c), src);
        cp_async16((uint32_t)__cvta_generic_to_shared(Ql + r * QKS + c), src + 64);
    }
    load_kv(0, 0);
    cp_commit();
    cp_wait<0>();
    __syncthreads();

    float oacc[2][4][4];
#pragma unroll
    for (int i = 0; i < 2; i++)
#pragma unroll
        for (int j = 0; j < 4; j++)
#pragma unroll
            for (int r = 0; r < 4; r++) oacc[i][j][r] = 0.0f;

    for (int jb = 0; jb < 32; jb++) {
        if (jb + 1 < 32) { load_kv(jb + 1, (jb + 1) & 1); cp_commit(); }

        const __nv_bfloat16* Kh = Kb + (jb & 1) * 2 * KPL;
        const __nv_bfloat16* Kl = Kh + KPL;
        const float* Vs = Vb + (jb & 1) * 64 * PSTR;

        // ---- scores (identical arithmetic to sums_kernel) ----
        float acc[2][4][4];
#pragma unroll
        for (int i = 0; i < 2; i++)
#pragma unroll
            for (int j = 0; j < 4; j++)
#pragma unroll
                for (int r = 0; r < 4; r++) acc[i][j][r] = 0.0f;

#pragma unroll
        for (int ks = 0; ks < 4; ks++) {
            const int k0 = ks * 16;
            uint32_t a_h[2][4], a_l[2][4], b_h[4][2], b_l[4][2];
#pragma unroll
            for (int mi = 0; mi < 2; mi++) {
                const int r0 = wm0 + mi * 16 + g;
                const int o0 = r0 * QKS + k0 + 2 * t;
                const int o1 = (r0 + 8) * QKS + k0 + 2 * t;
                a_h[mi][0] = *(const uint32_t*)(Qh + o0);
                a_h[mi][1] = *(const uint32_t*)(Qh + o1);
                a_h[mi][2] = *(const uint32_t*)(Qh + o0 + 8);
                a_h[mi][3] = *(const uint32_t*)(Qh + o1 + 8);
                a_l[mi][0] = *(const uint32_t*)(Ql + o0);
                a_l[mi][1] = *(const uint32_t*)(Ql + o1);
                a_l[mi][2] = *(const uint32_t*)(Ql + o0 + 8);
                a_l[mi][3] = *(const uint32_t*)(Ql + o1 + 8);
            }
#pragma unroll
            for (int ni = 0; ni < 4; ni++) {
                const int n0 = wn0 + ni * 8 + g;
                const int ob = n0 * QKS + k0 + 2 * t;
                b_h[ni][0] = *(const uint32_t*)(Kh + ob);
                b_h[ni][1] = *(const uint32_t*)(Kh + ob + 8);
                b_l[ni][0] = *(const uint32_t*)(Kl + ob);
                b_l[ni][1] = *(const uint32_t*)(Kl + ob + 8);
            }
#pragma unroll
            for (int mi = 0; mi < 2; mi++)
#pragma unroll
                for (int ni = 0; ni < 4; ni++) {
                    mma_bf16(acc[mi][ni], a_l[mi], b_h[ni]);
                    mma_bf16(acc[mi][ni], a_h[mi], b_l[ni]);
                    mma_bf16(acc[mi][ni], a_h[mi], b_h[ni]);
                }
        }

        // ---- normalize, store attn (once!), stash P in smem ----
#pragma unroll
        for (int mi = 0; mi < 2; mi++) {
#pragma unroll
            for (int ni = 0; ni < 4; ni++) {
                const int rl0 = wm0 + mi * 16 + g;
                const int cl0 = wn0 + ni * 8 + 2 * t;
                const float si0 = sInv[rl0], si1 = sInv[rl0 + 8];
                float p0 = __uint_as_float(f2tf32(__expf(0.125f * acc[mi][ni][0]) * si0));
                float p1 = __uint_as_float(f2tf32(__expf(0.125f * acc[mi][ni][1]) * si0));
                float p2 = __uint_as_float(f2tf32(__expf(0.125f * acc[mi][ni][2]) * si1));
                float p3 = __uint_as_float(f2tf32(__expf(0.125f * acc[mi][ni][3]) * si1));
                const long long grow0 = bm + rl0;
                const long long gcol = (long long)jb * 64 + cl0;
                float2 v0 = {p0, p1}, v1 = {p2, p3};
                *(float2*)(Ca + grow0 * S_LEN + gcol) = v0;
                *(float2*)(Ca + (grow0 + 8) * S_LEN + gcol) = v1;
                *(float2*)(Psm + rl0 * PSTR + cl0) = v0;
                *(float2*)(Psm + (rl0 + 8) * PSTR + cl0) = v1;
            }
        }
        __syncthreads();   // P tile ready for all warps

        // ---- PV: oacc += P(128x64) @ V(64x64), zero-ALU tf32 ----
#pragma unroll
        for (int ks = 0; ks < 8; ks++) {
            uint32_t ah[2][4], bh[4][2];
#pragma unroll
            for (int mi = 0; mi < 2; mi++) {
                const int r0 = wm0 + mi * 16 + g;
                const int c0 = ks * 8 + t;
                ah[mi][0] = __float_as_uint(Psm[(r0    ) * PSTR + c0    ]);
                ah[mi][1] = __float_as_uint(Psm[(r0 + 8) * PSTR + c0    ]);
                ah[mi][2] = __float_as_uint(Psm[(r0    ) * PSTR + c0 + 4]);
                ah[mi][3] = __float_as_uint(Psm[(r0 + 8) * PSTR + c0 + 4]);
            }
#pragma unroll
            for (int ni = 0; ni < 4; ni++) {
                const int n0 = wn0 + ni * 8 + g;
                bh[ni][0] = __float_as_uint(Vs[(ks * 8 + t    ) * PSTR + n0]);
                bh[ni][1] = __float_as_uint(Vs[(ks * 8 + t + 4) * PSTR + n0]);
            }
#pragma unroll
            for (int mi = 0; mi < 2; mi++)
#pragma unroll
                for (int ni = 0; ni < 4; ni++)
                    mma_tf32(oacc[mi][ni], ah[mi], bh[ni]);
        }

        if (jb + 1 < 32) cp_wait<0>();
        __syncthreads();   // PV reads done; buffers safe to reuse
    }

    // ---- epilogue: store output strip (tf32-rounded for fc PT) ----
#pragma unroll
    for (int mi = 0; mi < 2; mi++) {
#pragma unroll
        for (int ni = 0; ni < 4; ni++) {
            const int rl0 = wm0 + mi * 16 + g;
            const long long row0 = bm + rl0;
            const long long col0 = wn0 + ni * 8 + t * 2;
            float2 v0, v1;
            v0.x = __uint_as_float(f2tf32(oacc[mi][ni][0]));
            v0.y = __uint_as_float(f2tf32(oacc[mi][ni][1]));
            v1.x = __uint_as_float(f2tf32(oacc[mi][ni][2]));
            v1.y = __uint_as_float(f2tf32(oacc[mi][ni][3]));
            *(float2*)(Co + row0 * DMODEL + col0) = v0;
            *(float2*)(Co + (row0 + 8) * DMODEL + col0) = v1;
        }
    }
}

// =================================================================
// In-place LayerNorm over rows of length DMODEL (1024). 256 threads.
// =================================================================
__global__ __launch_bounds__(256) void ln_kernel(float* __restrict__ x,
                                                 const float* __restrict__ gamma,
                                                 const float* __restrict__ beta)
{
    float* row = x + (size_t)blockIdx.x * DMODEL;
    const int tid = threadIdx.x;
    __shared__ float ssum[8], ssq[8];

    float v[4];
    float s = 0.0f, sq = 0.0f;
#pragma unroll
    for (int j = 0; j < 4; j++) {
        v[j] = row[tid + j * 256];
        s += v[j];
        sq += v[j] * v[j];
    }
#pragma unroll
    for (int o = 16; o > 0; o >>= 1) {
        s  += __shfl_xor_sync(0xffffffffu, s, o);
        sq += __shfl_xor_sync(0xffffffffu, sq, o);
    }
    if ((tid & 31) == 0) { ssum[tid >> 5] = s; ssq[tid >> 5] = sq; }
    __syncthreads();
    s = 0.0f; sq = 0.0f;
#pragma unroll
    for (int j = 0; j < 8; j++) { s += ssum[j]; sq += ssq[j]; }

    const float mu = s * (1.0f / DMODEL);
    const float var = sq * (1.0f / DMODEL) - mu * mu;
    const float rstd = rsqrtf(var + 1e-6f);
#pragma unroll
    for (int j = 0; j < 4; j++) {
        const int c = tid + j * 256;
        row[c] = (v[j] - mu) * rstd * gamma[c] + beta[c];
    }
}

// =================================================================
static constexpr int GEMM_SMEM  = 2 * (128 * 36 + 64 * 36) * 4;          // 55296 B
static constexpr int PROJ_SMEM  = 2 * (2 * 128 * 40 + 2 * 64 * 40) * 2;  // 61440 B
static constexpr int SUMS_SMEM  = (2 * 128 * QKS + 2 * 2 * 64 * QKS) * 2;          // 73728 B
static constexpr int FUSED_SMEM = (2 * 128 * QKS + 2 * 2 * 64 * QKS) * 2
                                  + 128 * PSTR * 4 + 2 * 64 * PSTR * 4;  // 143360 B

extern "C" void kernel_launch(void* const* d_in, const int* in_sizes, int n_in,
                              void* d_out, int out_size)
{
    const float* q     = (const float*)d_in[0];
    const float* k     = (const float*)d_in[1];
    const float* v     = (const float*)d_in[2];
    const float* w_q   = (const float*)d_in[3];
    const float* w_k   = (const float*)d_in[4];
    const float* w_v   = (const float*)d_in[5];
    const float* w_fc  = (const float*)d_in[6];
    const float* gamma = (const float*)d_in[7];
    const float* beta  = (const float*)d_in[8];

    __nv_bfloat16 *qs, *ks_, *q2, *k2, *wq2, *wk2;
    float *vp, *ao, *wfr, *sinv;
    cudaGetSymbolAddress((void**)&qs, g_qs);
    cudaGetSymbolAddress((void**)&ks_, g_ks);
    cudaGetSymbolAddress((void**)&q2, g_q2);
    cudaGetSymbolAddress((void**)&k2, g_k2);
    cudaGetSymbolAddress((void**)&wq2, g_wq2);
    cudaGetSymbolAddress((void**)&wk2, g_wk2);
    cudaGetSymbolAddress((void**)&vp, g_vp);
    cudaGetSymbolAddress((void**)&ao, g_ao);
    cudaGetSymbolAddress((void**)&wfr, g_wf);
    cudaGetSymbolAddress((void**)&sinv, g_sinv);

    float* out  = (float*)d_out;
    float* attn = out + (size_t)MROWS * DMODEL;   // [B, H, Sq, Sk] fp32

    cudaFuncSetAttribute(proj_bf16_kernel,
                         cudaFuncAttributeMaxDynamicSharedMemorySize, PROJ_SMEM);
    cudaFuncSetAttribute(gemm_tc<true,false,true,false>,
                         cudaFuncAttributeMaxDynamicSharedMemorySize, GEMM_SMEM);
    cudaFuncSetAttribute(gemm_tc<true,true,false,true>,
                         cudaFuncAttributeMaxDynamicSharedMemorySize, GEMM_SMEM);
    cudaFuncSetAttribute(sums_kernel,
                         cudaFuncAttributeMaxDynamicSharedMemorySize, SUMS_SMEM);
    cudaFuncSetAttribute(fused_kernel,
                         cudaFuncAttributeMaxDynamicSharedMemorySize, FUSED_SMEM);

    dim3 blk(256);
    const int actBlocks = MROWS * (DMODEL / 4) / 256;   // 8192
    const int wBlocks   = DMODEL * (DMODEL / 4) / 256;  // 1024

    // --- split q, k, w_q, w_k into bf16 hi|lo planes; round w_fc ---
    split_planes<<<actBlocks, blk>>>(q, q2, MROWS);
    split_planes<<<actBlocks, blk>>>(k, k2, MROWS);
    split_planes<<<wBlocks, blk>>>(w_q, wq2, DMODEL);
    split_planes<<<wBlocks, blk>>>(w_k, wk2, DMODEL);
    round_tf32_kernel<<<wBlocks, blk>>>(w_fc, wfr, DMODEL * DMODEL / 4);

    // --- Q/K projections: zero-ALU bf16x3 GEMM from planes ---
    {
        dim3 g(DMODEL / 64, MROWS / 128, 1);
        proj_bf16_kernel<<<g, blk, PROJ_SMEM>>>(q2, wq2, qs);
        proj_bf16_kernel<<<g, blk, PROJ_SMEM>>>(k2, wk2, ks_);
    }
    // --- V projection (single tf32, output rounded to tf32) ---
    {
        dim3 g(DMODEL / 64, MROWS / 128, 1);
        gemm_tc<true,false,true,false><<<g, blk, GEMM_SMEM>>>(
            v, DMODEL, w_v, DMODEL, vp, DMODEL, DMODEL, 1.0f, nullptr);
    }

    // --- pass 1: softmax denominators (no attn store) ---
    {
        dim3 g(S_LEN / 128, NZ, 1);
        sums_kernel<<<g, blk, SUMS_SMEM>>>(qs, ks_, sinv);
    }

    // --- pass 2: recompute scores + write normalized attn once + PV ---
    {
        dim3 g(S_LEN / 128, NZ, 1);
        fused_kernel<<<g, blk, FUSED_SMEM>>>(qs, ks_, vp, sinv, attn, ao);
    }

    // --- fc + residual (zero-ALU tf32: pre-rounded ao and w_fc) ---
    {
        dim3 g(DMODEL / 64, MROWS / 128, 1);
        gemm_tc<true,true,false,true><<<g, blk, GEMM_SMEM>>>(
            ao, DMODEL, wfr, DMODEL, out, DMODEL, DMODEL, 1.0f, q);
    }

    // --- layernorm in place ---
    ln_kernel<<<MROWS, blk>>>(out, gamma, beta);
}